// round 14
// baseline (speedup 1.0000x reference)
#include <cuda_runtime.h>
#include <cuda_fp16.h>
#include <cstdint>

// Problem constants
constexpr int Bb = 2;
constexpr int Tt = 2048;
constexpr int DM = 1024;
constexpr int Hh = 16;
constexpr int HD = 64;
constexpr int MROWS = Bb * Tt;   // 4096

// Scratch (no allocation allowed -> __device__ globals)
__device__ __half g_x[MROWS * DM];
__device__ __half g_w[4 * DM * DM];   // Wq, Wk, Wv, Wo
__device__ __half g_q[MROWS * DM];    // pre-scaled by 1/8
__device__ __half g_k[MROWS * DM];
__device__ __half g_v[MROWS * DM];
__device__ __half g_a[MROWS * DM];

// ---------------------------------------------------------------------------
// PTX helpers
// ---------------------------------------------------------------------------
__device__ __forceinline__ uint32_t smem_u32(const void* p) {
    uint32_t a;
    asm("{ .reg .u64 t; cvta.to.shared.u64 t, %1; cvt.u32.u64 %0, t; }"
        : "=r"(a) : "l"(p));
    return a;
}

__device__ __forceinline__ void ldmat_x4(uint32_t* r, uint32_t addr) {
    asm volatile("ldmatrix.sync.aligned.m8n8.x4.shared.b16 {%0,%1,%2,%3}, [%4];"
                 : "=r"(r[0]), "=r"(r[1]), "=r"(r[2]), "=r"(r[3]) : "r"(addr));
}
__device__ __forceinline__ void ldmat_x4_t(uint32_t* r, uint32_t addr) {
    asm volatile("ldmatrix.sync.aligned.m8n8.x4.trans.shared.b16 {%0,%1,%2,%3}, [%4];"
                 : "=r"(r[0]), "=r"(r[1]), "=r"(r[2]), "=r"(r[3]) : "r"(addr));
}

__device__ __forceinline__ void mma_f16(float* c, const uint32_t* a, const uint32_t* b) {
    asm volatile(
        "mma.sync.aligned.m16n8k16.row.col.f32.f16.f16.f32 "
        "{%0,%1,%2,%3}, {%4,%5,%6,%7}, {%8,%9}, {%0,%1,%2,%3};"
        : "+f"(c[0]), "+f"(c[1]), "+f"(c[2]), "+f"(c[3])
        : "r"(a[0]), "r"(a[1]), "r"(a[2]), "r"(a[3]), "r"(b[0]), "r"(b[1]));
}

__device__ __forceinline__ void cp16(uint32_t dst, const void* src) {
    asm volatile("cp.async.cg.shared.global [%0], [%1], 16;" :: "r"(dst), "l"(src));
}
__device__ __forceinline__ void cp_commit() {
    asm volatile("cp.async.commit_group;");
}
template <int N> __device__ __forceinline__ void cp_wait() {
    asm volatile("cp.async.wait_group %0;" :: "n"(N));
}

__device__ __forceinline__ uint32_t pack_h2(float lo, float hi) {
    __half2 v = __floats2half2_rn(lo, hi);
    return *reinterpret_cast<uint32_t*>(&v);
}

// ---------------------------------------------------------------------------
// Convert fp32 -> fp16 : x AND the four weight matrices, one launch
// ---------------------------------------------------------------------------
__device__ __forceinline__ uint2 cvt4(const float4 v) {
    __half2 a = __floats2half2_rn(v.x, v.y);
    __half2 b = __floats2half2_rn(v.z, v.w);
    uint2 r;
    r.x = *reinterpret_cast<uint32_t*>(&a);
    r.y = *reinterpret_cast<uint32_t*>(&b);
    return r;
}

__global__ __launch_bounds__(256) void convert_all_kernel(
    const float* __restrict__ x,
    const float* __restrict__ w0, const float* __restrict__ w1,
    const float* __restrict__ w2, const float* __restrict__ w3)
{
    constexpr int NX4 = MROWS * DM / 4;   // 1,048,576
    constexpr int NW4 = DM * DM / 4;      // 262,144
    int i = blockIdx.x * blockDim.x + threadIdx.x;
    if (i < NX4) {
        ((uint2*)g_x)[i] = cvt4(((const float4*)x)[i]);
    } else {
        int j = i - NX4;
        int m = j >> 18;
        int r = j & (NW4 - 1);
        const float* src = (m == 0) ? w0 : (m == 1) ? w1 : (m == 2) ? w2 : w3;
        ((uint2*)g_w)[(size_t)m * NW4 + r] = cvt4(((const float4*)src)[r]);
    }
}

// ---------------------------------------------------------------------------
// mma.sync fp16 NT GEMM: CTA tile 128x128, 256 threads,
// 8 warps as 2x4 of 64x32 tiles, BK=32, double-buffered, 2 CTAs/SM.
// ---------------------------------------------------------------------------
constexpr int BK = 32;
constexpr int NCH = DM / BK;                   // 32
constexpr int RS = 40;                         // row stride in half elems (80 B)
constexpr uint32_t TILE_T = 128 * 80;          // 10240 per tensor
constexpr uint32_t STAGE_B = 2 * TILE_T;       // 20480 (A, B)
constexpr uint32_t GEMM_SMEM = 2 * STAGE_B;    // 40960

__device__ __forceinline__ void gemm_body(
    const __half* __restrict__ A,
    const __half* __restrict__ B,
    float* __restrict__ C,
    __half* __restrict__ outH,
    float scale, uint32_t sb, int row0, int col0)
{
    const int tid = threadIdx.x, lane = tid & 31, wid = tid >> 5;
    const int wr = wid & 1, wc = wid >> 1;        // 2x4 warp grid of 64x32
    const int m0w = wr * 64, n0w = wc * 32;

    float acc[4][4][4];
#pragma unroll
    for (int mi = 0; mi < 4; mi++)
#pragma unroll
        for (int ni = 0; ni < 4; ni++)
#pragma unroll
            for (int j = 0; j < 4; j++) acc[mi][ni][j] = 0.f;

    // per chunk: 2 tensors x 128 rows x 4 c16 = 1024 cp16; 4 per thread
    auto load_chunk = [&](int c, int stage) {
        const int k0 = c * BK;
        const uint32_t stg = sb + (uint32_t)stage * STAGE_B;
#pragma unroll
        for (int j = 0; j < 4; j++) {
            int idx = tid + j * 256;               // 0..1023
            int t = idx >> 9, r = (idx & 511) >> 2, c16 = idx & 3;
            const __half* s = t ? B : A;
            int rb = t ? col0 : row0;
            cp16(stg + (uint32_t)t * TILE_T + (uint32_t)(r * 80 + c16 * 16),
                 s + (size_t)(rb + r) * DM + k0 + c16 * 8);
        }
        cp_commit();
    };

    load_chunk(0, 0);

    for (int c = 0; c < NCH; c++) {
        if (c + 1 < NCH) { load_chunk(c + 1, (c + 1) & 1); cp_wait<1>(); }
        else             { cp_wait<0>(); }
        __syncthreads();

        const uint32_t stg = sb + (uint32_t)(c & 1) * STAGE_B;
        const uint32_t uA = stg, uB = stg + TILE_T;

        const int arow = m0w + (lane & 15);
        const int brow = n0w + (lane & 7) + ((lane >> 4) << 3);

#pragma unroll
        for (int kt = 0; kt < 2; kt++) {
            const int acol = kt * 16 + ((lane >> 4) << 3);
            const int bcol = kt * 16 + (((lane >> 3) & 1) << 3);
            uint32_t a[4][4];
#pragma unroll
            for (int mi = 0; mi < 4; mi++) {
                uint32_t off = (uint32_t)(((arow + mi * 16) * RS + acol) * 2);
                ldmat_x4(a[mi], uA + off);
            }
#pragma unroll
            for (int p = 0; p < 2; p++) {
                uint32_t off = (uint32_t)(((brow + p * 16) * RS + bcol) * 2);
                uint32_t r4[4];
                ldmat_x4(r4, uB + off);
                uint32_t b0[2] = {r4[0], r4[1]}, b1[2] = {r4[2], r4[3]};
#pragma unroll
                for (int mi = 0; mi < 4; mi++) {
                    mma_f16(acc[mi][2 * p],     a[mi], b0);
                    mma_f16(acc[mi][2 * p + 1], a[mi], b1);
                }
            }
        }
        __syncthreads();
    }

    const int g = lane >> 2, tg = lane & 3;
    if (outH) {
#pragma unroll
        for (int mi = 0; mi < 4; mi++) {
#pragma unroll
            for (int ni = 0; ni < 4; ni++) {
                int rgl = row0 + m0w + mi * 16 + g;
                int cgl = col0 + n0w + ni * 8 + tg * 2;
#pragma unroll
                for (int half = 0; half < 2; half++) {
                    float v0 = acc[mi][ni][2 * half + 0] * scale;
                    float v1 = acc[mi][ni][2 * half + 1] * scale;
                    __half2 hv = __floats2half2_rn(v0, v1);
                    *(__half2*)&outH[(size_t)(rgl + 8 * half) * DM + cgl] = hv;
                }
            }
        }
    } else {
#pragma unroll
        for (int mi = 0; mi < 4; mi++) {
#pragma unroll
            for (int ni = 0; ni < 4; ni++) {
                int rgl = row0 + m0w + mi * 16 + g;
                int cgl = col0 + n0w + ni * 8 + tg * 2;
                *(float2*)&C[(size_t)rgl * DM + cgl] =
                    make_float2(acc[mi][ni][0], acc[mi][ni][1]);
                *(float2*)&C[(size_t)(rgl + 8) * DM + cgl] =
                    make_float2(acc[mi][ni][2], acc[mi][ni][3]);
            }
        }
    }
}

__global__ __launch_bounds__(256, 2)
void qkv_fused_kernel()
{
    extern __shared__ __align__(128) char smem[];
    const uint32_t sb = smem_u32(smem);
    const int z = blockIdx.z;
    const __half* w = g_w + (size_t)z * DM * DM;
    __half* oh = (z == 0) ? g_q : (z == 1) ? g_k : g_v;
    float scale = (z == 0) ? 0.125f : 1.0f;
    gemm_body(g_x, w, nullptr, oh, scale, sb,
              blockIdx.y * 128, blockIdx.x * 128);
}

__global__ __launch_bounds__(256, 2)
void oproj_kernel(float* __restrict__ out)
{
    extern __shared__ __align__(128) char smem[];
    const uint32_t sb = smem_u32(smem);
    gemm_body(g_a, g_w + (size_t)3 * DM * DM, out, nullptr, 1.0f, sb,
              blockIdx.y * 128, blockIdx.x * 128);
}

// ---------------------------------------------------------------------------
// Tensor-core flash attention (fp16): 256 threads, 8 warps x 16 query rows,
// CTA = 128 queries, key blocks of 64, double-buffered K/V, 2 CTAs/SM.
// smem: Q 18432 + 2 stages x 18432 = 55296.
// ---------------------------------------------------------------------------
constexpr uint32_t QT   = 128 * 144;           // 18432 Q tensor
constexpr uint32_t KVT  = 64 * 144;            // 9216 per KV tensor
constexpr uint32_t STG  = 2 * KVT;             // 18432 per stage (K, V)
constexpr uint32_t ATTN_SMEM = QT + 2 * STG;   // 55296

__global__ __launch_bounds__(256, 2)
void attn_mma_kernel(const unsigned char* __restrict__ pad)
{
    extern __shared__ __align__(128) char dsm[];
    __shared__ float pmadd[2][64];
    const uint32_t sb = smem_u32(dsm);
    const int tid = threadIdx.x, lane = tid & 31, w = tid >> 5;
    const int qb = gridDim.x - 1 - blockIdx.x;   // heavy tiles first
    const int bh = blockIdx.y, b = bh >> 4, h = bh & 15;
    const int qw0 = w * 16;                      // warp's 16 query rows
    const int qt0 = qb * 128;
    const int g = lane >> 2, tg = lane & 3;

    // ---- Load Q tile (128 rows) ----
    {
#pragma unroll
        for (int j = 0; j < 4; j++) {
            int idx = tid + j * 256;
            int r = idx >> 3, c16 = idx & 7;
            const __half* src =
                g_q + (size_t)(b * Tt + qt0 + r) * DM + h * HD + c16 * 8;
            cp16(sb + (uint32_t)(r * 144 + c16 * 16), src);
        }
        cp_commit();
    }

    auto load_kv = [&](int kb2, int st) {
#pragma unroll
        for (int j = 0; j < 4; j++) {
            int idx = tid + j * 256;
            int t = idx >> 9, r = (idx & 511) >> 3, c16 = idx & 7;
            const __half* src = (t ? g_v : g_k)
                + (size_t)(b * Tt + kb2 * 64 + r) * DM + h * HD + c16 * 8;
            cp16(sb + QT + (uint32_t)(st * (int)STG + t * (int)KVT + r * 144 + c16 * 16), src);
        }
        if (tid < 64)
            pmadd[st][tid] = pad[b * Tt + kb2 * 64 + tid] ? -INFINITY : 0.f;
        cp_commit();
    };

    float m0 = -INFINITY, m1 = -INFINITY, l0 = 0.f, l1 = 0.f;
    float oacc[8][4];
#pragma unroll
    for (int j = 0; j < 8; j++)
#pragma unroll
        for (int cc = 0; cc < 4; cc++) oacc[j][cc] = 0.f;

    const int nkb = 2 * qb + 2;
    load_kv(0, 0);

    for (int kb = 0; kb < nkb; kb++) {
        if (kb + 1 < nkb) { load_kv(kb + 1, (kb + 1) & 1); cp_wait<1>(); }
        else              { cp_wait<0>(); }
        __syncthreads();

        const uint32_t st = sb + QT + (uint32_t)(kb & 1) * STG;
        const int kg0 = kb * 64;

        if (kg0 <= qt0 + qw0 + 15) {
            // ---- S = Q K^T ----
            float sacc[8][4];
#pragma unroll
            for (int j = 0; j < 8; j++)
#pragma unroll
                for (int cc = 0; cc < 4; cc++) sacc[j][cc] = 0.f;

            const int brow = (lane & 7) + ((lane >> 4) << 3);
            const uint32_t qoff0 = (uint32_t)((qw0 + (lane & 15)) * 144 + ((lane >> 4) << 4));
#pragma unroll
            for (int kt = 0; kt < 4; kt++) {
                uint32_t q4[4];
                ldmat_x4(q4, sb + qoff0 + kt * 32);
                const int bcol = kt * 16 + (((lane >> 3) & 1) << 3);
#pragma unroll
                for (int p = 0; p < 4; p++) {
                    uint32_t off = (uint32_t)((brow + p * 16) * 144 + bcol * 2);
                    uint32_t r4[4];
                    ldmat_x4(r4, st + off);
                    uint32_t b0[2] = {r4[0], r4[1]}, b1[2] = {r4[2], r4[3]};
                    mma_f16(sacc[2 * p],     q4, b0);
                    mma_f16(sacc[2 * p + 1], q4, b1);
                }
            }

            // ---- mask + padding ----
            const bool needmask = (kg0 + 63 > qt0 + qw0);
            const int qg0r = qt0 + qw0 + g;
            const int qg1r = qg0r + 8;
#pragma unroll
            for (int j = 0; j < 8; j++) {
                int lc = j * 8 + tg * 2;
                float pm0 = pmadd[kb & 1][lc];
                float pm1 = pmadd[kb & 1][lc + 1];
                sacc[j][0] += pm0; sacc[j][1] += pm1;
                sacc[j][2] += pm0; sacc[j][3] += pm1;
                if (needmask) {
                    int c0 = kg0 + lc;
                    if (c0     > qg0r) sacc[j][0] = -INFINITY;
                    if (c0 + 1 > qg0r) sacc[j][1] = -INFINITY;
                    if (c0     > qg1r) sacc[j][2] = -INFINITY;
                    if (c0 + 1 > qg1r) sacc[j][3] = -INFINITY;
                }
            }

            // ---- online softmax ----
            float mx0 = -INFINITY, mx1 = -INFINITY;
#pragma unroll
            for (int j = 0; j < 8; j++) {
                mx0 = fmaxf(mx0, fmaxf(sacc[j][0], sacc[j][1]));
                mx1 = fmaxf(mx1, fmaxf(sacc[j][2], sacc[j][3]));
            }
            mx0 = fmaxf(mx0, __shfl_xor_sync(0xffffffffu, mx0, 1));
            mx0 = fmaxf(mx0, __shfl_xor_sync(0xffffffffu, mx0, 2));
            mx1 = fmaxf(mx1, __shfl_xor_sync(0xffffffffu, mx1, 1));
            mx1 = fmaxf(mx1, __shfl_xor_sync(0xffffffffu, mx1, 2));

            float m0n = fmaxf(m0, mx0), m1n = fmaxf(m1, mx1);
            float a0 = __expf(m0 - m0n), a1 = __expf(m1 - m1n);

            float s0 = 0.f, s1 = 0.f;
#pragma unroll
            for (int j = 0; j < 8; j++) {
                sacc[j][0] = __expf(sacc[j][0] - m0n);
                sacc[j][1] = __expf(sacc[j][1] - m0n);
                sacc[j][2] = __expf(sacc[j][2] - m1n);
                sacc[j][3] = __expf(sacc[j][3] - m1n);
                s0 += sacc[j][0] + sacc[j][1];
                s1 += sacc[j][2] + sacc[j][3];
            }
            s0 += __shfl_xor_sync(0xffffffffu, s0, 1);
            s0 += __shfl_xor_sync(0xffffffffu, s0, 2);
            s1 += __shfl_xor_sync(0xffffffffu, s1, 1);
            s1 += __shfl_xor_sync(0xffffffffu, s1, 2);

            l0 = l0 * a0 + s0;  l1 = l1 * a1 + s1;
            m0 = m0n;  m1 = m1n;
#pragma unroll
            for (int j = 0; j < 8; j++) {
                oacc[j][0] *= a0; oacc[j][1] *= a0;
                oacc[j][2] *= a1; oacc[j][3] *= a1;
            }

            // ---- O += P V ----
            const uint32_t vb = st + KVT;
#pragma unroll
            for (int kt = 0; kt < 4; kt++) {
                uint32_t ph[4];
#pragma unroll
                for (int hf = 0; hf < 2; hf++) {
                    const float* s = sacc[2 * kt + hf];
                    ph[2 * hf + 0] = pack_h2(s[0], s[1]);
                    ph[2 * hf + 1] = pack_h2(s[2], s[3]);
                }
                const int vrow = kt * 16 + (lane & 15);
#pragma unroll
                for (int p = 0; p < 4; p++) {
                    uint32_t off = (uint32_t)(vrow * 144 + (p * 16 + ((lane >> 4) << 3)) * 2);
                    uint32_t r4[4];
                    ldmat_x4_t(r4, vb + off);
                    uint32_t v0[2] = {r4[0], r4[1]}, v1[2] = {r4[2], r4[3]};
                    mma_f16(oacc[2 * p],     ph, v0);
                    mma_f16(oacc[2 * p + 1], ph, v1);
                }
            }
        }
        __syncthreads();
    }

    // ---- epilogue: normalize, emit fp16 ----
    float inv0 = 1.f / l0, inv1 = 1.f / l1;
    const int row0 = b * Tt + qt0 + qw0 + g;
#pragma unroll
    for (int j = 0; j < 8; j++) {
        int col = h * HD + j * 8 + tg * 2;
        __half2 hv0 = __floats2half2_rn(oacc[j][0] * inv0, oacc[j][1] * inv0);
        __half2 hv1 = __floats2half2_rn(oacc[j][2] * inv1, oacc[j][3] * inv1);
        *(__half2*)&g_a[(size_t)row0 * DM + col] = hv0;
        *(__half2*)&g_a[(size_t)(row0 + 8) * DM + col] = hv1;
    }
}

// ---------------------------------------------------------------------------
// Launch
// ---------------------------------------------------------------------------
extern "C" void kernel_launch(void* const* d_in, const int* in_sizes, int n_in,
                              void* d_out, int out_size)
{
    const float* x  = (const float*)d_in[0];
    const unsigned char* pad = (const unsigned char*)d_in[1];
    const float* Wq = (const float*)d_in[2];
    const float* Wk = (const float*)d_in[3];
    const float* Wv = (const float*)d_in[4];
    const float* Wo = (const float*)d_in[5];
    float* out = (float*)d_out;

    cudaFuncSetAttribute(qkv_fused_kernel,
                         cudaFuncAttributeMaxDynamicSharedMemorySize, GEMM_SMEM);
    cudaFuncSetAttribute(oproj_kernel,
                         cudaFuncAttributeMaxDynamicSharedMemorySize, GEMM_SMEM);
    cudaFuncSetAttribute(attn_mma_kernel,
                         cudaFuncAttributeMaxDynamicSharedMemorySize, ATTN_SMEM);

    convert_all_kernel<<<8192, 256>>>(x, Wq, Wk, Wv, Wo);

    dim3 gg(DM / 128, MROWS / 128, 3);     // 8 x 32 x 3 = 768 CTAs
    qkv_fused_kernel<<<gg, 256, GEMM_SMEM>>>();

    dim3 attn_grid(Tt / 128, Bb * Hh);     // 16 x 32 = 512 CTAs
    attn_mma_kernel<<<attn_grid, 256, ATTN_SMEM>>>(pad);

    dim3 og(DM / 128, MROWS / 128);        // 8 x 32 = 256 CTAs
    oproj_kernel<<<og, 256, GEMM_SMEM>>>(out);
}

// round 16
// speedup vs baseline: 1.0638x; 1.0638x over previous
#include <cuda_runtime.h>
#include <cuda_fp16.h>
#include <cstdint>

// Problem constants
constexpr int Bb = 2;
constexpr int Tt = 2048;
constexpr int DM = 1024;
constexpr int Hh = 16;
constexpr int HD = 64;
constexpr int MROWS = Bb * Tt;   // 4096

// Scratch (no allocation allowed -> __device__ globals)
__device__ __half g_x[MROWS * DM];
__device__ __half g_w[4 * DM * DM];   // Wq, Wk, Wv, Wo
__device__ __half g_q[MROWS * DM];    // pre-scaled by 1/8
__device__ __half g_k[MROWS * DM];
__device__ __half g_v[MROWS * DM];
__device__ __half g_a[MROWS * DM];

// ---------------------------------------------------------------------------
// PTX helpers
// ---------------------------------------------------------------------------
__device__ __forceinline__ uint32_t smem_u32(const void* p) {
    uint32_t a;
    asm("{ .reg .u64 t; cvta.to.shared.u64 t, %1; cvt.u32.u64 %0, t; }"
        : "=r"(a) : "l"(p));
    return a;
}

__device__ __forceinline__ void ldmat_x4(uint32_t* r, uint32_t addr) {
    asm volatile("ldmatrix.sync.aligned.m8n8.x4.shared.b16 {%0,%1,%2,%3}, [%4];"
                 : "=r"(r[0]), "=r"(r[1]), "=r"(r[2]), "=r"(r[3]) : "r"(addr));
}
__device__ __forceinline__ void ldmat_x4_t(uint32_t* r, uint32_t addr) {
    asm volatile("ldmatrix.sync.aligned.m8n8.x4.trans.shared.b16 {%0,%1,%2,%3}, [%4];"
                 : "=r"(r[0]), "=r"(r[1]), "=r"(r[2]), "=r"(r[3]) : "r"(addr));
}

__device__ __forceinline__ void mma_f16(float* c, const uint32_t* a, const uint32_t* b) {
    asm volatile(
        "mma.sync.aligned.m16n8k16.row.col.f32.f16.f16.f32 "
        "{%0,%1,%2,%3}, {%4,%5,%6,%7}, {%8,%9}, {%0,%1,%2,%3};"
        : "+f"(c[0]), "+f"(c[1]), "+f"(c[2]), "+f"(c[3])
        : "r"(a[0]), "r"(a[1]), "r"(a[2]), "r"(a[3]), "r"(b[0]), "r"(b[1]));
}

__device__ __forceinline__ void cp16(uint32_t dst, const void* src) {
    asm volatile("cp.async.cg.shared.global [%0], [%1], 16;" :: "r"(dst), "l"(src));
}
__device__ __forceinline__ void cp_commit() {
    asm volatile("cp.async.commit_group;");
}
template <int N> __device__ __forceinline__ void cp_wait() {
    asm volatile("cp.async.wait_group %0;" :: "n"(N));
}

__device__ __forceinline__ uint32_t pack_h2(float lo, float hi) {
    __half2 v = __floats2half2_rn(lo, hi);
    return *reinterpret_cast<uint32_t*>(&v);
}

// ---------------------------------------------------------------------------
// Convert fp32 -> fp16 : x AND the four weight matrices, one launch
// ---------------------------------------------------------------------------
__device__ __forceinline__ uint2 cvt4(const float4 v) {
    __half2 a = __floats2half2_rn(v.x, v.y);
    __half2 b = __floats2half2_rn(v.z, v.w);
    uint2 r;
    r.x = *reinterpret_cast<uint32_t*>(&a);
    r.y = *reinterpret_cast<uint32_t*>(&b);
    return r;
}

__global__ __launch_bounds__(256) void convert_all_kernel(
    const float* __restrict__ x,
    const float* __restrict__ w0, const float* __restrict__ w1,
    const float* __restrict__ w2, const float* __restrict__ w3)
{
    constexpr int NX4 = MROWS * DM / 4;   // 1,048,576
    constexpr int NW4 = DM * DM / 4;      // 262,144
    int i = blockIdx.x * blockDim.x + threadIdx.x;
    if (i < NX4) {
        ((uint2*)g_x)[i] = cvt4(((const float4*)x)[i]);
    } else {
        int j = i - NX4;
        int m = j >> 18;
        int r = j & (NW4 - 1);
        const float* src = (m == 0) ? w0 : (m == 1) ? w1 : (m == 2) ? w2 : w3;
        ((uint2*)g_w)[(size_t)m * NW4 + r] = cvt4(((const float4*)src)[r]);
    }
}

// ---------------------------------------------------------------------------
// mma.sync fp16 NT GEMM: CTA tile 128x128, 128 threads,
// 4 warps as 2x2 of 64x64 tiles, BK=64, double-buffered, 2 CTAs/SM.
// Row stride 144 B (72 halves) -> conflict-free ldmatrix.
// ---------------------------------------------------------------------------
constexpr int BK = 64;
constexpr int NCH = DM / BK;                   // 16
constexpr int RSG = 72;                        // row stride in half elems (144 B)
constexpr uint32_t TILE_T = 128 * 144;         // 18432 per tensor per stage
constexpr uint32_t STAGE_B = 2 * TILE_T;       // 36864 (A, B)
constexpr uint32_t GEMM_SMEM = 2 * STAGE_B;    // 73728

__device__ __forceinline__ void gemm_body(
    const __half* __restrict__ A,
    const __half* __restrict__ B,
    float* __restrict__ C,
    __half* __restrict__ outH,
    float scale, uint32_t sb, int row0, int col0)
{
    const int tid = threadIdx.x, lane = tid & 31, wid = tid >> 5;
    const int wr = wid & 1, wc = wid >> 1;        // 2x2 warp grid of 64x64
    const int m0w = wr * 64, n0w = wc * 64;

    float acc[4][8][4];
#pragma unroll
    for (int mi = 0; mi < 4; mi++)
#pragma unroll
        for (int ni = 0; ni < 8; ni++)
#pragma unroll
            for (int j = 0; j < 4; j++) acc[mi][ni][j] = 0.f;

    // per chunk: 2 tensors x 128 rows x 8 c16 = 2048 cp16; 16 per thread
    auto load_chunk = [&](int c, int stage) {
        const int k0 = c * BK;
        const uint32_t stg = sb + (uint32_t)stage * STAGE_B;
#pragma unroll
        for (int j = 0; j < 16; j++) {
            int idx = tid + j * 128;               // 0..2047
            int t = idx >> 10, r = (idx & 1023) >> 3, c16 = idx & 7;
            const __half* s = t ? B : A;
            int rb = t ? col0 : row0;
            cp16(stg + (uint32_t)t * TILE_T + (uint32_t)(r * 144 + c16 * 16),
                 s + (size_t)(rb + r) * DM + k0 + c16 * 8);
        }
        cp_commit();
    };

    load_chunk(0, 0);

    for (int c = 0; c < NCH; c++) {
        if (c + 1 < NCH) { load_chunk(c + 1, (c + 1) & 1); cp_wait<1>(); }
        else             { cp_wait<0>(); }
        __syncthreads();

        const uint32_t stg = sb + (uint32_t)(c & 1) * STAGE_B;
        const uint32_t uA = stg, uB = stg + TILE_T;

        const int arow = m0w + (lane & 15);
        const int brow = n0w + (lane & 7) + ((lane >> 4) << 3);

#pragma unroll
        for (int kt = 0; kt < 4; kt++) {
            const int acol = kt * 16 + ((lane >> 4) << 3);
            const int bcol = kt * 16 + (((lane >> 3) & 1) << 3);
            uint32_t a[4][4];
#pragma unroll
            for (int mi = 0; mi < 4; mi++) {
                uint32_t off = (uint32_t)(((arow + mi * 16) * RSG + acol) * 2);
                ldmat_x4(a[mi], uA + off);
            }
#pragma unroll
            for (int p = 0; p < 4; p++) {
                uint32_t off = (uint32_t)(((brow + p * 16) * RSG + bcol) * 2);
                uint32_t r4[4];
                ldmat_x4(r4, uB + off);
                uint32_t b0[2] = {r4[0], r4[1]}, b1[2] = {r4[2], r4[3]};
#pragma unroll
                for (int mi = 0; mi < 4; mi++) {
                    mma_f16(acc[mi][2 * p],     a[mi], b0);
                    mma_f16(acc[mi][2 * p + 1], a[mi], b1);
                }
            }
        }
        __syncthreads();
    }

    const int g = lane >> 2, tg = lane & 3;
    if (outH) {
#pragma unroll
        for (int mi = 0; mi < 4; mi++) {
#pragma unroll
            for (int ni = 0; ni < 8; ni++) {
                int rgl = row0 + m0w + mi * 16 + g;
                int cgl = col0 + n0w + ni * 8 + tg * 2;
#pragma unroll
                for (int half = 0; half < 2; half++) {
                    float v0 = acc[mi][ni][2 * half + 0] * scale;
                    float v1 = acc[mi][ni][2 * half + 1] * scale;
                    __half2 hv = __floats2half2_rn(v0, v1);
                    *(__half2*)&outH[(size_t)(rgl + 8 * half) * DM + cgl] = hv;
                }
            }
        }
    } else {
#pragma unroll
        for (int mi = 0; mi < 4; mi++) {
#pragma unroll
            for (int ni = 0; ni < 8; ni++) {
                int rgl = row0 + m0w + mi * 16 + g;
                int cgl = col0 + n0w + ni * 8 + tg * 2;
                *(float2*)&C[(size_t)rgl * DM + cgl] =
                    make_float2(acc[mi][ni][0], acc[mi][ni][1]);
                *(float2*)&C[(size_t)(rgl + 8) * DM + cgl] =
                    make_float2(acc[mi][ni][2], acc[mi][ni][3]);
            }
        }
    }
}

__global__ __launch_bounds__(128, 2)
void qkv_fused_kernel()
{
    extern __shared__ __align__(128) char smem[];
    const uint32_t sb = smem_u32(smem);
    const int z = blockIdx.z;
    const __half* w = g_w + (size_t)z * DM * DM;
    __half* oh = (z == 0) ? g_q : (z == 1) ? g_k : g_v;
    float scale = (z == 0) ? 0.125f : 1.0f;
    gemm_body(g_x, w, nullptr, oh, scale, sb,
              blockIdx.y * 128, blockIdx.x * 128);
}

__global__ __launch_bounds__(128, 2)
void oproj_kernel(float* __restrict__ out)
{
    extern __shared__ __align__(128) char smem[];
    const uint32_t sb = smem_u32(smem);
    gemm_body(g_a, g_w + (size_t)3 * DM * DM, out, nullptr, 1.0f, sb,
              blockIdx.y * 128, blockIdx.x * 128);
}

// ---------------------------------------------------------------------------
// Tensor-core flash attention (fp16): 128 threads, 4 warps x 32 query rows,
// CTA = 128 queries, key blocks of 64, 3-stage KV pipeline, 2 CTAs/SM.
// smem: Q 18432 + 3 stages x 18432 = 73728.
// ---------------------------------------------------------------------------
constexpr uint32_t QT   = 128 * 144;           // 18432 Q tensor
constexpr uint32_t KVT  = 64 * 144;            // 9216 per KV tensor
constexpr uint32_t STG  = 2 * KVT;             // 18432 per stage (K, V)
constexpr uint32_t ATTN_SMEM = QT + 3 * STG;   // 73728

__global__ __launch_bounds__(128, 2)
void attn_mma_kernel(const unsigned char* __restrict__ pad)
{
    extern __shared__ __align__(128) char dsm[];
    __shared__ float pmadd[3][64];
    const uint32_t sb = smem_u32(dsm);
    const int tid = threadIdx.x, lane = tid & 31, w = tid >> 5;
    const int qb = gridDim.x - 1 - blockIdx.x;   // heavy tiles first
    const int bh = blockIdx.y, b = bh >> 4, h = bh & 15;
    const int qw0 = w * 32;                      // warp's 32 query rows
    const int qt0 = qb * 128;
    const int g = lane >> 2, tg = lane & 3;

    // ---- Load Q tile (128 rows) ----
    {
#pragma unroll
        for (int j = 0; j < 8; j++) {
            int idx = tid + j * 128;
            int r = idx >> 3, c16 = idx & 7;
            const __half* src =
                g_q + (size_t)(b * Tt + qt0 + r) * DM + h * HD + c16 * 8;
            cp16(sb + (uint32_t)(r * 144 + c16 * 16), src);
        }
        cp_commit();
    }

    auto load_kv = [&](int kb2, int st) {
#pragma unroll
        for (int j = 0; j < 8; j++) {
            int idx = tid + j * 128;
            int t = idx >> 9, r = (idx & 511) >> 3, c16 = idx & 7;
            const __half* src = (t ? g_v : g_k)
                + (size_t)(b * Tt + kb2 * 64 + r) * DM + h * HD + c16 * 8;
            cp16(sb + QT + (uint32_t)(st * (int)STG + t * (int)KVT + r * 144 + c16 * 16), src);
        }
        if (tid < 64)
            pmadd[st][tid] = pad[b * Tt + kb2 * 64 + tid] ? -INFINITY : 0.f;
        cp_commit();
    };

    float m[2][2], l[2][2];
#pragma unroll
    for (int mi = 0; mi < 2; mi++) {
        m[mi][0] = -INFINITY; m[mi][1] = -INFINITY;
        l[mi][0] = 0.f; l[mi][1] = 0.f;
    }
    float oacc[2][8][4];
#pragma unroll
    for (int mi = 0; mi < 2; mi++)
#pragma unroll
        for (int j = 0; j < 8; j++)
#pragma unroll
            for (int cc = 0; cc < 4; cc++) oacc[mi][j][cc] = 0.f;

    const int nkb = 2 * qb + 2;
    load_kv(0, 0);
    if (nkb > 1) load_kv(1, 1);

    for (int kb = 0; kb < nkb; kb++) {
        if (kb + 2 < nkb)      { load_kv(kb + 2, (kb + 2) % 3); cp_wait<2>(); }
        else if (kb + 1 < nkb) { cp_wait<1>(); }
        else                   { cp_wait<0>(); }
        __syncthreads();

        const uint32_t st = sb + QT + (uint32_t)(kb % 3) * STG;
        const int kg0 = kb * 64;

        if (kg0 <= qt0 + qw0 + 31) {
            // ---- S = Q K^T ----
            float sacc[2][8][4];
#pragma unroll
            for (int mi = 0; mi < 2; mi++)
#pragma unroll
                for (int j = 0; j < 8; j++)
#pragma unroll
                    for (int cc = 0; cc < 4; cc++) sacc[mi][j][cc] = 0.f;

            const int brow = (lane & 7) + ((lane >> 4) << 3);
#pragma unroll
            for (int kt = 0; kt < 4; kt++) {
                uint32_t q4[2][4];
#pragma unroll
                for (int mi = 0; mi < 2; mi++) {
                    uint32_t off = (uint32_t)((qw0 + mi * 16 + (lane & 15)) * 144
                                              + kt * 32 + ((lane >> 4) << 4));
                    ldmat_x4(q4[mi], sb + off);
                }
                const int bcol = kt * 16 + (((lane >> 3) & 1) << 3);
#pragma unroll
                for (int p = 0; p < 4; p++) {
                    uint32_t off = (uint32_t)((brow + p * 16) * 144 + bcol * 2);
                    uint32_t r4[4];
                    ldmat_x4(r4, st + off);
                    uint32_t b0[2] = {r4[0], r4[1]}, b1[2] = {r4[2], r4[3]};
#pragma unroll
                    for (int mi = 0; mi < 2; mi++) {
                        mma_f16(sacc[mi][2 * p],     q4[mi], b0);
                        mma_f16(sacc[mi][2 * p + 1], q4[mi], b1);
                    }
                }
            }

            // ---- mask + padding + softmax per m-subtile ----
#pragma unroll
            for (int mi = 0; mi < 2; mi++) {
                const int qrow0 = qt0 + qw0 + mi * 16;
                const bool needmask = (kg0 + 63 > qrow0);
                const int qg0r = qrow0 + g;
                const int qg1r = qg0r + 8;
#pragma unroll
                for (int j = 0; j < 8; j++) {
                    int lc = j * 8 + tg * 2;
                    float pm0 = pmadd[kb % 3][lc];
                    float pm1 = pmadd[kb % 3][lc + 1];
                    sacc[mi][j][0] += pm0; sacc[mi][j][1] += pm1;
                    sacc[mi][j][2] += pm0; sacc[mi][j][3] += pm1;
                    if (needmask) {
                        int c0 = kg0 + lc;
                        if (c0     > qg0r) sacc[mi][j][0] = -INFINITY;
                        if (c0 + 1 > qg0r) sacc[mi][j][1] = -INFINITY;
                        if (c0     > qg1r) sacc[mi][j][2] = -INFINITY;
                        if (c0 + 1 > qg1r) sacc[mi][j][3] = -INFINITY;
                    }
                }

                float mx0 = -INFINITY, mx1 = -INFINITY;
#pragma unroll
                for (int j = 0; j < 8; j++) {
                    mx0 = fmaxf(mx0, fmaxf(sacc[mi][j][0], sacc[mi][j][1]));
                    mx1 = fmaxf(mx1, fmaxf(sacc[mi][j][2], sacc[mi][j][3]));
                }
                mx0 = fmaxf(mx0, __shfl_xor_sync(0xffffffffu, mx0, 1));
                mx0 = fmaxf(mx0, __shfl_xor_sync(0xffffffffu, mx0, 2));
                mx1 = fmaxf(mx1, __shfl_xor_sync(0xffffffffu, mx1, 1));
                mx1 = fmaxf(mx1, __shfl_xor_sync(0xffffffffu, mx1, 2));

                float m0n = fmaxf(m[mi][0], mx0), m1n = fmaxf(m[mi][1], mx1);
                float a0 = __expf(m[mi][0] - m0n), a1 = __expf(m[mi][1] - m1n);

                float s0 = 0.f, s1 = 0.f;
#pragma unroll
                for (int j = 0; j < 8; j++) {
                    sacc[mi][j][0] = __expf(sacc[mi][j][0] - m0n);
                    sacc[mi][j][1] = __expf(sacc[mi][j][1] - m0n);
                    sacc[mi][j][2] = __expf(sacc[mi][j][2] - m1n);
                    sacc[mi][j][3] = __expf(sacc[mi][j][3] - m1n);
                    s0 += sacc[mi][j][0] + sacc[mi][j][1];
                    s1 += sacc[mi][j][2] + sacc[mi][j][3];
                }
                s0 += __shfl_xor_sync(0xffffffffu, s0, 1);
                s0 += __shfl_xor_sync(0xffffffffu, s0, 2);
                s1 += __shfl_xor_sync(0xffffffffu, s1, 1);
                s1 += __shfl_xor_sync(0xffffffffu, s1, 2);

                l[mi][0] = l[mi][0] * a0 + s0;
                l[mi][1] = l[mi][1] * a1 + s1;
                m[mi][0] = m0n; m[mi][1] = m1n;
#pragma unroll
                for (int j = 0; j < 8; j++) {
                    oacc[mi][j][0] *= a0; oacc[mi][j][1] *= a0;
                    oacc[mi][j][2] *= a1; oacc[mi][j][3] *= a1;
                }
            }

            // ---- O += P V ----
            const uint32_t vb = st + KVT;
#pragma unroll
            for (int kt = 0; kt < 4; kt++) {
                uint32_t ph[2][4];
#pragma unroll
                for (int mi = 0; mi < 2; mi++) {
#pragma unroll
                    for (int hf = 0; hf < 2; hf++) {
                        const float* s = sacc[mi][2 * kt + hf];
                        ph[mi][2 * hf + 0] = pack_h2(s[0], s[1]);
                        ph[mi][2 * hf + 1] = pack_h2(s[2], s[3]);
                    }
                }
                const int vrow = kt * 16 + (lane & 15);
#pragma unroll
                for (int p = 0; p < 4; p++) {
                    uint32_t off = (uint32_t)(vrow * 144 + (p * 16 + ((lane >> 4) << 3)) * 2);
                    uint32_t r4[4];
                    ldmat_x4_t(r4, vb + off);
                    uint32_t v0[2] = {r4[0], r4[1]}, v1[2] = {r4[2], r4[3]};
#pragma unroll
                    for (int mi = 0; mi < 2; mi++) {
                        mma_f16(oacc[mi][2 * p],     ph[mi], v0);
                        mma_f16(oacc[mi][2 * p + 1], ph[mi], v1);
                    }
                }
            }
        }
        __syncthreads();
    }

    // ---- epilogue: normalize, emit fp16 ----
#pragma unroll
    for (int mi = 0; mi < 2; mi++) {
        float inv0 = 1.f / l[mi][0], inv1 = 1.f / l[mi][1];
        const int row0 = b * Tt + qt0 + qw0 + mi * 16 + g;
#pragma unroll
        for (int j = 0; j < 8; j++) {
            int col = h * HD + j * 8 + tg * 2;
            __half2 hv0 = __floats2half2_rn(oacc[mi][j][0] * inv0, oacc[mi][j][1] * inv0);
            __half2 hv1 = __floats2half2_rn(oacc[mi][j][2] * inv1, oacc[mi][j][3] * inv1);
            *(__half2*)&g_a[(size_t)row0 * DM + col] = hv0;
            *(__half2*)&g_a[(size_t)(row0 + 8) * DM + col] = hv1;
        }
    }
}

// ---------------------------------------------------------------------------
// Launch
// ---------------------------------------------------------------------------
extern "C" void kernel_launch(void* const* d_in, const int* in_sizes, int n_in,
                              void* d_out, int out_size)
{
    const float* x  = (const float*)d_in[0];
    const unsigned char* pad = (const unsigned char*)d_in[1];
    const float* Wq = (const float*)d_in[2];
    const float* Wk = (const float*)d_in[3];
    const float* Wv = (const float*)d_in[4];
    const float* Wo = (const float*)d_in[5];
    float* out = (float*)d_out;

    cudaFuncSetAttribute(qkv_fused_kernel,
                         cudaFuncAttributeMaxDynamicSharedMemorySize, GEMM_SMEM);
    cudaFuncSetAttribute(oproj_kernel,
                         cudaFuncAttributeMaxDynamicSharedMemorySize, GEMM_SMEM);
    cudaFuncSetAttribute(attn_mma_kernel,
                         cudaFuncAttributeMaxDynamicSharedMemorySize, ATTN_SMEM);

    convert_all_kernel<<<8192, 256>>>(x, Wq, Wk, Wv, Wo);

    dim3 gg(DM / 128, MROWS / 128, 3);     // 8 x 32 x 3 = 768 CTAs
    qkv_fused_kernel<<<gg, 128, GEMM_SMEM>>>();

    dim3 attn_grid(Tt / 128, Bb * Hh);     // 16 x 32 = 512 CTAs
    attn_mma_kernel<<<attn_grid, 128, ATTN_SMEM>>>(pad);

    dim3 og(DM / 128, MROWS / 128);        // 8 x 32 = 256 CTAs
    oproj_kernel<<<og, 128, GEMM_SMEM>>>(out);
}

// round 17
// speedup vs baseline: 1.1058x; 1.0395x over previous
#include <cuda_runtime.h>
#include <cuda_fp16.h>
#include <cstdint>

// Problem constants
constexpr int Bb = 2;
constexpr int Tt = 2048;
constexpr int DM = 1024;
constexpr int Hh = 16;
constexpr int HD = 64;
constexpr int MROWS = Bb * Tt;   // 4096

// Scratch (no allocation allowed -> __device__ globals)
__device__ __half g_x[MROWS * DM];
__device__ __half g_w[4 * DM * DM];   // Wq, Wk, Wv, Wo
__device__ __half g_q[MROWS * DM];    // pre-scaled by 1/8
__device__ __half g_k[MROWS * DM];
__device__ __half g_v[MROWS * DM];
__device__ __half g_a[MROWS * DM];

// ---------------------------------------------------------------------------
// PTX helpers
// ---------------------------------------------------------------------------
__device__ __forceinline__ uint32_t smem_u32(const void* p) {
    uint32_t a;
    asm("{ .reg .u64 t; cvta.to.shared.u64 t, %1; cvt.u32.u64 %0, t; }"
        : "=r"(a) : "l"(p));
    return a;
}

__device__ __forceinline__ void ldmat_x4(uint32_t* r, uint32_t addr) {
    asm volatile("ldmatrix.sync.aligned.m8n8.x4.shared.b16 {%0,%1,%2,%3}, [%4];"
                 : "=r"(r[0]), "=r"(r[1]), "=r"(r[2]), "=r"(r[3]) : "r"(addr));
}
__device__ __forceinline__ void ldmat_x4_t(uint32_t* r, uint32_t addr) {
    asm volatile("ldmatrix.sync.aligned.m8n8.x4.trans.shared.b16 {%0,%1,%2,%3}, [%4];"
                 : "=r"(r[0]), "=r"(r[1]), "=r"(r[2]), "=r"(r[3]) : "r"(addr));
}

__device__ __forceinline__ void mma_f16(float* c, const uint32_t* a, const uint32_t* b) {
    asm volatile(
        "mma.sync.aligned.m16n8k16.row.col.f32.f16.f16.f32 "
        "{%0,%1,%2,%3}, {%4,%5,%6,%7}, {%8,%9}, {%0,%1,%2,%3};"
        : "+f"(c[0]), "+f"(c[1]), "+f"(c[2]), "+f"(c[3])
        : "r"(a[0]), "r"(a[1]), "r"(a[2]), "r"(a[3]), "r"(b[0]), "r"(b[1]));
}

__device__ __forceinline__ void cp16(uint32_t dst, const void* src) {
    asm volatile("cp.async.cg.shared.global [%0], [%1], 16;" :: "r"(dst), "l"(src));
}
__device__ __forceinline__ void cp_commit() {
    asm volatile("cp.async.commit_group;");
}
template <int N> __device__ __forceinline__ void cp_wait() {
    asm volatile("cp.async.wait_group %0;" :: "n"(N));
}

__device__ __forceinline__ uint32_t pack_h2(float lo, float hi) {
    __half2 v = __floats2half2_rn(lo, hi);
    return *reinterpret_cast<uint32_t*>(&v);
}

// ---------------------------------------------------------------------------
// Convert fp32 -> fp16 : x AND the four weight matrices, one launch
// ---------------------------------------------------------------------------
__device__ __forceinline__ uint2 cvt4(const float4 v) {
    __half2 a = __floats2half2_rn(v.x, v.y);
    __half2 b = __floats2half2_rn(v.z, v.w);
    uint2 r;
    r.x = *reinterpret_cast<uint32_t*>(&a);
    r.y = *reinterpret_cast<uint32_t*>(&b);
    return r;
}

__global__ __launch_bounds__(256) void convert_all_kernel(
    const float* __restrict__ x,
    const float* __restrict__ w0, const float* __restrict__ w1,
    const float* __restrict__ w2, const float* __restrict__ w3)
{
    constexpr int NX4 = MROWS * DM / 4;   // 1,048,576
    constexpr int NW4 = DM * DM / 4;      // 262,144
    int i = blockIdx.x * blockDim.x + threadIdx.x;
    if (i < NX4) {
        ((uint2*)g_x)[i] = cvt4(((const float4*)x)[i]);
    } else {
        int j = i - NX4;
        int m = j >> 18;
        int r = j & (NW4 - 1);
        const float* src = (m == 0) ? w0 : (m == 1) ? w1 : (m == 2) ? w2 : w3;
        ((uint2*)g_w)[(size_t)m * NW4 + r] = cvt4(((const float4*)src)[r]);
    }
}

// ---------------------------------------------------------------------------
// mma.sync fp16 NT GEMM: CTA tile 128x128, 128 threads,
// 4 warps as 2x2 of 64x64 tiles, BK=32.
// 4-stage smem ring, prefetch distance 2, ONE barrier per chunk.
// (Overwrite target (c+2)&3 is disjoint from laggards' read stage (c-1)&3.)
// ---------------------------------------------------------------------------
constexpr int BK = 32;
constexpr int NCH = DM / BK;                   // 32
constexpr int RS = 40;                         // row stride in half elems (80 B)
constexpr uint32_t TILE_T = 128 * 80;          // 10240 per tensor
constexpr uint32_t STAGE_B = 2 * TILE_T;       // 20480 (A, B)
constexpr uint32_t GEMM_SMEM = 4 * STAGE_B;    // 81920

__device__ __forceinline__ void gemm_body(
    const __half* __restrict__ A,
    const __half* __restrict__ B,
    float* __restrict__ C,
    __half* __restrict__ outH,
    float scale, uint32_t sb, int row0, int col0)
{
    const int tid = threadIdx.x, lane = tid & 31, wid = tid >> 5;
    const int wr = wid & 1, wc = wid >> 1;        // 2x2 warp grid of 64x64
    const int m0w = wr * 64, n0w = wc * 64;

    float acc[4][8][4];
#pragma unroll
    for (int mi = 0; mi < 4; mi++)
#pragma unroll
        for (int ni = 0; ni < 8; ni++)
#pragma unroll
            for (int j = 0; j < 4; j++) acc[mi][ni][j] = 0.f;

    // per chunk: 2 tensors x 128 rows x 4 c16 = 1024 cp16; 8 per thread
    auto load_chunk = [&](int c, int stage) {
        const int k0 = c * BK;
        const uint32_t stg = sb + (uint32_t)stage * STAGE_B;
#pragma unroll
        for (int j = 0; j < 8; j++) {
            int idx = tid + j * 128;               // 0..1023
            int t = idx >> 9, r = (idx & 511) >> 2, c16 = idx & 3;
            const __half* s = t ? B : A;
            int rb = t ? col0 : row0;
            cp16(stg + (uint32_t)t * TILE_T + (uint32_t)(r * 80 + c16 * 16),
                 s + (size_t)(rb + r) * DM + k0 + c16 * 8);
        }
        cp_commit();
    };

    load_chunk(0, 0);
    load_chunk(1, 1);

    for (int c = 0; c < NCH; c++) {
        if (c + 2 < NCH)      { load_chunk(c + 2, (c + 2) & 3); cp_wait<2>(); }
        else if (c + 1 < NCH) { cp_wait<1>(); }
        else                  { cp_wait<0>(); }
        __syncthreads();   // single barrier per chunk

        const uint32_t stg = sb + (uint32_t)(c & 3) * STAGE_B;
        const uint32_t uA = stg, uB = stg + TILE_T;

        const int arow = m0w + (lane & 15);
        const int brow = n0w + (lane & 7) + ((lane >> 4) << 3);

#pragma unroll
        for (int kt = 0; kt < 2; kt++) {
            const int acol = kt * 16 + ((lane >> 4) << 3);
            const int bcol = kt * 16 + (((lane >> 3) & 1) << 3);
            uint32_t a[4][4];
#pragma unroll
            for (int mi = 0; mi < 4; mi++) {
                uint32_t off = (uint32_t)(((arow + mi * 16) * RS + acol) * 2);
                ldmat_x4(a[mi], uA + off);
            }
#pragma unroll
            for (int p = 0; p < 4; p++) {
                uint32_t off = (uint32_t)(((brow + p * 16) * RS + bcol) * 2);
                uint32_t r4[4];
                ldmat_x4(r4, uB + off);
                uint32_t b0[2] = {r4[0], r4[1]}, b1[2] = {r4[2], r4[3]};
#pragma unroll
                for (int mi = 0; mi < 4; mi++) {
                    mma_f16(acc[mi][2 * p],     a[mi], b0);
                    mma_f16(acc[mi][2 * p + 1], a[mi], b1);
                }
            }
        }
        // no trailing barrier: stage (c+2)&3 written next iter differs from
        // any stage still being read by warps at most one chunk behind.
    }

    const int g = lane >> 2, tg = lane & 3;
    if (outH) {
#pragma unroll
        for (int mi = 0; mi < 4; mi++) {
#pragma unroll
            for (int ni = 0; ni < 8; ni++) {
                int rgl = row0 + m0w + mi * 16 + g;
                int cgl = col0 + n0w + ni * 8 + tg * 2;
#pragma unroll
                for (int half = 0; half < 2; half++) {
                    float v0 = acc[mi][ni][2 * half + 0] * scale;
                    float v1 = acc[mi][ni][2 * half + 1] * scale;
                    __half2 hv = __floats2half2_rn(v0, v1);
                    *(__half2*)&outH[(size_t)(rgl + 8 * half) * DM + cgl] = hv;
                }
            }
        }
    } else {
#pragma unroll
        for (int mi = 0; mi < 4; mi++) {
#pragma unroll
            for (int ni = 0; ni < 8; ni++) {
                int rgl = row0 + m0w + mi * 16 + g;
                int cgl = col0 + n0w + ni * 8 + tg * 2;
                *(float2*)&C[(size_t)rgl * DM + cgl] =
                    make_float2(acc[mi][ni][0], acc[mi][ni][1]);
                *(float2*)&C[(size_t)(rgl + 8) * DM + cgl] =
                    make_float2(acc[mi][ni][2], acc[mi][ni][3]);
            }
        }
    }
}

__global__ __launch_bounds__(128, 2)
void qkv_fused_kernel()
{
    extern __shared__ __align__(128) char smem[];
    const uint32_t sb = smem_u32(smem);
    const int z = blockIdx.z;
    const __half* w = g_w + (size_t)z * DM * DM;
    __half* oh = (z == 0) ? g_q : (z == 1) ? g_k : g_v;
    float scale = (z == 0) ? 0.125f : 1.0f;
    gemm_body(g_x, w, nullptr, oh, scale, sb,
              blockIdx.y * 128, blockIdx.x * 128);
}

__global__ __launch_bounds__(128, 2)
void oproj_kernel(float* __restrict__ out)
{
    extern __shared__ __align__(128) char smem[];
    const uint32_t sb = smem_u32(smem);
    gemm_body(g_a, g_w + (size_t)3 * DM * DM, out, nullptr, 1.0f, sb,
              blockIdx.y * 128, blockIdx.x * 128);
}

// ---------------------------------------------------------------------------
// Tensor-core flash attention (fp16): 128 threads, 4 warps x 32 query rows,
// CTA = 128 queries, key blocks of 64, double-buffered K/V, 2 CTAs/SM.
// (R13-identical.)
// ---------------------------------------------------------------------------
constexpr uint32_t QT   = 128 * 144;           // 18432 Q tensor
constexpr uint32_t KVT  = 64 * 144;            // 9216 per KV tensor
constexpr uint32_t STG  = 2 * KVT;             // 18432 per stage (K, V)
constexpr uint32_t ATTN_SMEM = QT + 2 * STG;   // 55296

__global__ __launch_bounds__(128, 2)
void attn_mma_kernel(const unsigned char* __restrict__ pad)
{
    extern __shared__ __align__(128) char dsm[];
    __shared__ float pmadd[2][64];
    const uint32_t sb = smem_u32(dsm);
    const int tid = threadIdx.x, lane = tid & 31, w = tid >> 5;
    const int qb = gridDim.x - 1 - blockIdx.x;   // heavy tiles first
    const int bh = blockIdx.y, b = bh >> 4, h = bh & 15;
    const int qw0 = w * 32;                      // warp's 32 query rows
    const int qt0 = qb * 128;
    const int g = lane >> 2, tg = lane & 3;

    // ---- Load Q tile (128 rows) ----
    {
#pragma unroll
        for (int j = 0; j < 8; j++) {
            int idx = tid + j * 128;
            int r = idx >> 3, c16 = idx & 7;
            const __half* src =
                g_q + (size_t)(b * Tt + qt0 + r) * DM + h * HD + c16 * 8;
            cp16(sb + (uint32_t)(r * 144 + c16 * 16), src);
        }
        cp_commit();
    }

    auto load_kv = [&](int kb2, int st) {
#pragma unroll
        for (int j = 0; j < 8; j++) {
            int idx = tid + j * 128;
            int t = idx >> 9, r = (idx & 511) >> 3, c16 = idx & 7;
            const __half* src = (t ? g_v : g_k)
                + (size_t)(b * Tt + kb2 * 64 + r) * DM + h * HD + c16 * 8;
            cp16(sb + QT + (uint32_t)(st * (int)STG + t * (int)KVT + r * 144 + c16 * 16), src);
        }
        if (tid < 64)
            pmadd[st][tid] = pad[b * Tt + kb2 * 64 + tid] ? -INFINITY : 0.f;
        cp_commit();
    };

    float m[2][2], l[2][2];
#pragma unroll
    for (int mi = 0; mi < 2; mi++) {
        m[mi][0] = -INFINITY; m[mi][1] = -INFINITY;
        l[mi][0] = 0.f; l[mi][1] = 0.f;
    }
    float oacc[2][8][4];
#pragma unroll
    for (int mi = 0; mi < 2; mi++)
#pragma unroll
        for (int j = 0; j < 8; j++)
#pragma unroll
            for (int cc = 0; cc < 4; cc++) oacc[mi][j][cc] = 0.f;

    const int nkb = 2 * qb + 2;
    load_kv(0, 0);

    for (int kb = 0; kb < nkb; kb++) {
        if (kb + 1 < nkb) { load_kv(kb + 1, (kb + 1) & 1); cp_wait<1>(); }
        else              { cp_wait<0>(); }
        __syncthreads();

        const uint32_t st = sb + QT + (uint32_t)(kb & 1) * STG;
        const int kg0 = kb * 64;

        if (kg0 <= qt0 + qw0 + 31) {
            // ---- S = Q K^T ----
            float sacc[2][8][4];
#pragma unroll
            for (int mi = 0; mi < 2; mi++)
#pragma unroll
                for (int j = 0; j < 8; j++)
#pragma unroll
                    for (int cc = 0; cc < 4; cc++) sacc[mi][j][cc] = 0.f;

            const int brow = (lane & 7) + ((lane >> 4) << 3);
#pragma unroll
            for (int kt = 0; kt < 4; kt++) {
                uint32_t q4[2][4];
#pragma unroll
                for (int mi = 0; mi < 2; mi++) {
                    uint32_t off = (uint32_t)((qw0 + mi * 16 + (lane & 15)) * 144
                                              + kt * 32 + ((lane >> 4) << 4));
                    ldmat_x4(q4[mi], sb + off);
                }
                const int bcol = kt * 16 + (((lane >> 3) & 1) << 3);
#pragma unroll
                for (int p = 0; p < 4; p++) {
                    uint32_t off = (uint32_t)((brow + p * 16) * 144 + bcol * 2);
                    uint32_t r4[4];
                    ldmat_x4(r4, st + off);
                    uint32_t b0[2] = {r4[0], r4[1]}, b1[2] = {r4[2], r4[3]};
#pragma unroll
                    for (int mi = 0; mi < 2; mi++) {
                        mma_f16(sacc[mi][2 * p],     q4[mi], b0);
                        mma_f16(sacc[mi][2 * p + 1], q4[mi], b1);
                    }
                }
            }

            // ---- mask + padding + softmax per m-subtile ----
#pragma unroll
            for (int mi = 0; mi < 2; mi++) {
                const int qrow0 = qt0 + qw0 + mi * 16;
                const bool needmask = (kg0 + 63 > qrow0);
                const int qg0r = qrow0 + g;
                const int qg1r = qg0r + 8;
#pragma unroll
                for (int j = 0; j < 8; j++) {
                    int lc = j * 8 + tg * 2;
                    float pm0 = pmadd[kb & 1][lc];
                    float pm1 = pmadd[kb & 1][lc + 1];
                    sacc[mi][j][0] += pm0; sacc[mi][j][1] += pm1;
                    sacc[mi][j][2] += pm0; sacc[mi][j][3] += pm1;
                    if (needmask) {
                        int c0 = kg0 + lc;
                        if (c0     > qg0r) sacc[mi][j][0] = -INFINITY;
                        if (c0 + 1 > qg0r) sacc[mi][j][1] = -INFINITY;
                        if (c0     > qg1r) sacc[mi][j][2] = -INFINITY;
                        if (c0 + 1 > qg1r) sacc[mi][j][3] = -INFINITY;
                    }
                }

                float mx0 = -INFINITY, mx1 = -INFINITY;
#pragma unroll
                for (int j = 0; j < 8; j++) {
                    mx0 = fmaxf(mx0, fmaxf(sacc[mi][j][0], sacc[mi][j][1]));
                    mx1 = fmaxf(mx1, fmaxf(sacc[mi][j][2], sacc[mi][j][3]));
                }
                mx0 = fmaxf(mx0, __shfl_xor_sync(0xffffffffu, mx0, 1));
                mx0 = fmaxf(mx0, __shfl_xor_sync(0xffffffffu, mx0, 2));
                mx1 = fmaxf(mx1, __shfl_xor_sync(0xffffffffu, mx1, 1));
                mx1 = fmaxf(mx1, __shfl_xor_sync(0xffffffffu, mx1, 2));

                float m0n = fmaxf(m[mi][0], mx0), m1n = fmaxf(m[mi][1], mx1);
                float a0 = __expf(m[mi][0] - m0n), a1 = __expf(m[mi][1] - m1n);

                float s0 = 0.f, s1 = 0.f;
#pragma unroll
                for (int j = 0; j < 8; j++) {
                    sacc[mi][j][0] = __expf(sacc[mi][j][0] - m0n);
                    sacc[mi][j][1] = __expf(sacc[mi][j][1] - m0n);
                    sacc[mi][j][2] = __expf(sacc[mi][j][2] - m1n);
                    sacc[mi][j][3] = __expf(sacc[mi][j][3] - m1n);
                    s0 += sacc[mi][j][0] + sacc[mi][j][1];
                    s1 += sacc[mi][j][2] + sacc[mi][j][3];
                }
                s0 += __shfl_xor_sync(0xffffffffu, s0, 1);
                s0 += __shfl_xor_sync(0xffffffffu, s0, 2);
                s1 += __shfl_xor_sync(0xffffffffu, s1, 1);
                s1 += __shfl_xor_sync(0xffffffffu, s1, 2);

                l[mi][0] = l[mi][0] * a0 + s0;
                l[mi][1] = l[mi][1] * a1 + s1;
                m[mi][0] = m0n; m[mi][1] = m1n;
#pragma unroll
                for (int j = 0; j < 8; j++) {
                    oacc[mi][j][0] *= a0; oacc[mi][j][1] *= a0;
                    oacc[mi][j][2] *= a1; oacc[mi][j][3] *= a1;
                }
            }

            // ---- O += P V ----
            const uint32_t vb = st + KVT;
#pragma unroll
            for (int kt = 0; kt < 4; kt++) {
                uint32_t ph[2][4];
#pragma unroll
                for (int mi = 0; mi < 2; mi++) {
#pragma unroll
                    for (int hf = 0; hf < 2; hf++) {
                        const float* s = sacc[mi][2 * kt + hf];
                        ph[mi][2 * hf + 0] = pack_h2(s[0], s[1]);
                        ph[mi][2 * hf + 1] = pack_h2(s[2], s[3]);
                    }
                }
                const int vrow = kt * 16 + (lane & 15);
#pragma unroll
                for (int p = 0; p < 4; p++) {
                    uint32_t off = (uint32_t)(vrow * 144 + (p * 16 + ((lane >> 4) << 3)) * 2);
                    uint32_t r4[4];
                    ldmat_x4_t(r4, vb + off);
                    uint32_t v0[2] = {r4[0], r4[1]}, v1[2] = {r4[2], r4[3]};
#pragma unroll
                    for (int mi = 0; mi < 2; mi++) {
                        mma_f16(oacc[mi][2 * p],     ph[mi], v0);
                        mma_f16(oacc[mi][2 * p + 1], ph[mi], v1);
                    }
                }
            }
        }
        __syncthreads();
    }

    // ---- epilogue: normalize, emit fp16 ----
#pragma unroll
    for (int mi = 0; mi < 2; mi++) {
        float inv0 = 1.f / l[mi][0], inv1 = 1.f / l[mi][1];
        const int row0 = b * Tt + qt0 + qw0 + mi * 16 + g;
#pragma unroll
        for (int j = 0; j < 8; j++) {
            int col = h * HD + j * 8 + tg * 2;
            __half2 hv0 = __floats2half2_rn(oacc[mi][j][0] * inv0, oacc[mi][j][1] * inv0);
            __half2 hv1 = __floats2half2_rn(oacc[mi][j][2] * inv1, oacc[mi][j][3] * inv1);
            *(__half2*)&g_a[(size_t)row0 * DM + col] = hv0;
            *(__half2*)&g_a[(size_t)(row0 + 8) * DM + col] = hv1;
        }
    }
}

// ---------------------------------------------------------------------------
// Launch
// ---------------------------------------------------------------------------
extern "C" void kernel_launch(void* const* d_in, const int* in_sizes, int n_in,
                              void* d_out, int out_size)
{
    const float* x  = (const float*)d_in[0];
    const unsigned char* pad = (const unsigned char*)d_in[1];
    const float* Wq = (const float*)d_in[2];
    const float* Wk = (const float*)d_in[3];
    const float* Wv = (const float*)d_in[4];
    const float* Wo = (const float*)d_in[5];
    float* out = (float*)d_out;

    cudaFuncSetAttribute(qkv_fused_kernel,
                         cudaFuncAttributeMaxDynamicSharedMemorySize, GEMM_SMEM);
    cudaFuncSetAttribute(oproj_kernel,
                         cudaFuncAttributeMaxDynamicSharedMemorySize, GEMM_SMEM);
    cudaFuncSetAttribute(attn_mma_kernel,
                         cudaFuncAttributeMaxDynamicSharedMemorySize, ATTN_SMEM);

    convert_all_kernel<<<8192, 256>>>(x, Wq, Wk, Wv, Wo);

    dim3 gg(DM / 128, MROWS / 128, 3);     // 8 x 32 x 3 = 768 CTAs
    qkv_fused_kernel<<<gg, 128, GEMM_SMEM>>>();

    dim3 attn_grid(Tt / 128, Bb * Hh);     // 16 x 32 = 512 CTAs
    attn_mma_kernel<<<attn_grid, 128, ATTN_SMEM>>>(pad);

    dim3 og(DM / 128, MROWS / 128);        // 8 x 32 = 256 CTAs
    oproj_kernel<<<og, 128, GEMM_SMEM>>>(out);
}